// round 2
// baseline (speedup 1.0000x reference)
#include <cuda_runtime.h>
#include <math.h>

// Problem dims (fixed by the dataset)
#define B_DIM   16
#define L_DIM   1024
#define D_DIM   256
#define H_DIM   256
#define KWIN    16
#define R_TOTAL (B_DIM * L_DIM)   // 16384 independent GRU chains
#define G3      (3 * H_DIM)       // 768

// GEMM tile config
#define BM 128
#define BN 64
#define BK 16
#define TM 8
#define TN 4

// Scratch (allocation-free rule: device globals)
__device__ float g_G[R_TOTAL * G3];            // 48 MB: precomputed input projections (incl. b_ih)
__device__ float g_H[2][R_TOTAL * H_DIM];      // 2 x 16 MB ping-pong hidden state

__device__ __forceinline__ float sigm(float x) {
    return 1.0f / (1.0f + __expf(-x));
}

// ---------------------------------------------------------------------------
// Kernel 1: projection GEMM  G[row, g*256+n] = sum_d x[row,d]*W_ih[g*256+n,d] + b_ih
// A = x [16384, 256] (K-contig), B = W_ih [768, 256] (K-contig)  -> NT GEMM
// ---------------------------------------------------------------------------
__global__ __launch_bounds__(256) void proj_kernel(
    const float* __restrict__ X,
    const float* __restrict__ Wih,
    const float* __restrict__ bih)
{
    __shared__ __align__(16) float As[BK][BM];
    __shared__ __align__(16) float Bs[3][BK][BN];

    const int tid = threadIdx.x;
    const int tx = tid & 15, ty = tid >> 4;
    const int gm = blockIdx.x * BM;
    const int n0 = blockIdx.y * BN;
    const int lrow = tid >> 2;        // 0..63
    const int kq = (tid & 3) << 2;    // 0,4,8,12

    float acc[3][TM][TN];
#pragma unroll
    for (int g = 0; g < 3; g++)
#pragma unroll
        for (int i = 0; i < TM; i++)
#pragma unroll
            for (int j = 0; j < TN; j++) acc[g][i][j] = 0.0f;

    for (int k0 = 0; k0 < D_DIM; k0 += BK) {
#pragma unroll
        for (int i = 0; i < 2; i++) {
            int r = lrow + i * 64;
            float4 v = *(const float4*)&X[(size_t)(gm + r) * D_DIM + k0 + kq];
            As[kq + 0][r] = v.x; As[kq + 1][r] = v.y;
            As[kq + 2][r] = v.z; As[kq + 3][r] = v.w;
        }
#pragma unroll
        for (int g = 0; g < 3; g++) {
            float4 v = *(const float4*)&Wih[(size_t)(g * H_DIM + n0 + lrow) * D_DIM + k0 + kq];
            Bs[g][kq + 0][lrow] = v.x; Bs[g][kq + 1][lrow] = v.y;
            Bs[g][kq + 2][lrow] = v.z; Bs[g][kq + 3][lrow] = v.w;
        }
        __syncthreads();
#pragma unroll
        for (int kk = 0; kk < BK; kk++) {
            float a[TM];
            *(float4*)&a[0] = *(const float4*)&As[kk][ty * TM];
            *(float4*)&a[4] = *(const float4*)&As[kk][ty * TM + 4];
#pragma unroll
            for (int g = 0; g < 3; g++) {
                float b[TN];
                *(float4*)&b[0] = *(const float4*)&Bs[g][kk][tx * TN];
#pragma unroll
                for (int i = 0; i < TM; i++)
#pragma unroll
                    for (int j = 0; j < TN; j++)
                        acc[g][i][j] = fmaf(a[i], b[j], acc[g][i][j]);
            }
        }
        __syncthreads();
    }

    const int col = n0 + tx * TN;
#pragma unroll
    for (int i = 0; i < TM; i++) {
        int row = gm + ty * TM + i;
#pragma unroll
        for (int g = 0; g < 3; g++) {
            float4 bv = *(const float4*)&bih[g * H_DIM + col];
            float o[4];
#pragma unroll
            for (int j = 0; j < TN; j++) o[j] = acc[g][i][j] + ((const float*)&bv)[j];
            *(float4*)&g_G[(size_t)row * G3 + g * H_DIM + col] =
                make_float4(o[0], o[1], o[2], o[3]);
        }
    }
}

// ---------------------------------------------------------------------------
// Kernel 2: window step t=0 (h=0 so gh=0; pure elementwise)
// h1 = (1-z)*tanh(gi_n + r*b_hh_n),  r=sig(gi_r+b_hh_r), z=sig(gi_z+b_hh_z)
// ---------------------------------------------------------------------------
__global__ __launch_bounds__(256) void step0_kernel(
    const float* __restrict__ bih,
    const float* __restrict__ bhh)
{
    const int row = blockIdx.x;
    const int col = threadIdx.x;
    const int l = row & (L_DIM - 1);
    const int src = l - (KWIN - 1);

    float gir, giz, gin;
    if (src >= 0) {
        const float* Gp = &g_G[(size_t)(row - l + src) * G3 + col];
        gir = Gp[0]; giz = Gp[H_DIM]; gin = Gp[2 * H_DIM];
    } else {
        gir = bih[col]; giz = bih[col + H_DIM]; gin = bih[col + 2 * H_DIM];
    }
    float r  = sigm(gir + bhh[col]);
    float z  = sigm(giz + bhh[col + H_DIM]);
    float nn = tanhf(gin + r * bhh[col + 2 * H_DIM]);
    g_H[0][(size_t)row * H_DIM + col] = (1.0f - z) * nn;
}

// ---------------------------------------------------------------------------
// Kernel 3: fused step GEMM + GRU update for window step t (1..15)
//   gh = h @ W_hh^T  (3 gates fused),  then GRU update, write H_out (or d_out)
// ---------------------------------------------------------------------------
__global__ __launch_bounds__(256) void step_kernel(
    const float* __restrict__ Whh,
    const float* __restrict__ bih,
    const float* __restrict__ bhh,
    int t, int in_idx, float* __restrict__ fin)
{
    const float* __restrict__ Hin = g_H[in_idx];
    float* __restrict__ Hout = fin ? fin : g_H[in_idx ^ 1];

    __shared__ __align__(16) float As[BK][BM];
    __shared__ __align__(16) float Bs[3][BK][BN];

    const int tid = threadIdx.x;
    const int tx = tid & 15, ty = tid >> 4;
    const int gm = blockIdx.x * BM;
    const int n0 = blockIdx.y * BN;
    const int lrow = tid >> 2;
    const int kq = (tid & 3) << 2;

    float acc[3][TM][TN];
#pragma unroll
    for (int g = 0; g < 3; g++)
#pragma unroll
        for (int i = 0; i < TM; i++)
#pragma unroll
            for (int j = 0; j < TN; j++) acc[g][i][j] = 0.0f;

    for (int k0 = 0; k0 < H_DIM; k0 += BK) {
#pragma unroll
        for (int i = 0; i < 2; i++) {
            int r = lrow + i * 64;
            float4 v = *(const float4*)&Hin[(size_t)(gm + r) * H_DIM + k0 + kq];
            As[kq + 0][r] = v.x; As[kq + 1][r] = v.y;
            As[kq + 2][r] = v.z; As[kq + 3][r] = v.w;
        }
#pragma unroll
        for (int g = 0; g < 3; g++) {
            float4 v = *(const float4*)&Whh[(size_t)(g * H_DIM + n0 + lrow) * H_DIM + k0 + kq];
            Bs[g][kq + 0][lrow] = v.x; Bs[g][kq + 1][lrow] = v.y;
            Bs[g][kq + 2][lrow] = v.z; Bs[g][kq + 3][lrow] = v.w;
        }
        __syncthreads();
#pragma unroll
        for (int kk = 0; kk < BK; kk++) {
            float a[TM];
            *(float4*)&a[0] = *(const float4*)&As[kk][ty * TM];
            *(float4*)&a[4] = *(const float4*)&As[kk][ty * TM + 4];
#pragma unroll
            for (int g = 0; g < 3; g++) {
                float b[TN];
                *(float4*)&b[0] = *(const float4*)&Bs[g][kk][tx * TN];
#pragma unroll
                for (int i = 0; i < TM; i++)
#pragma unroll
                    for (int j = 0; j < TN; j++)
                        acc[g][i][j] = fmaf(a[i], b[j], acc[g][i][j]);
            }
        }
        __syncthreads();
    }

    // GRU update epilogue
    const int col = n0 + tx * TN;
    float4 bh_r = *(const float4*)&bhh[col];
    float4 bh_z = *(const float4*)&bhh[col + H_DIM];
    float4 bh_n = *(const float4*)&bhh[col + 2 * H_DIM];
    float4 bi_r = *(const float4*)&bih[col];
    float4 bi_z = *(const float4*)&bih[col + H_DIM];
    float4 bi_n = *(const float4*)&bih[col + 2 * H_DIM];

#pragma unroll
    for (int i = 0; i < TM; i++) {
        int row = gm + ty * TM + i;
        int l = row & (L_DIM - 1);
        int src = l + t - (KWIN - 1);
        float4 gr, gz, gn;
        if (src >= 0) {
            const float* Gp = &g_G[(size_t)(row - l + src) * G3 + col];
            gr = *(const float4*)(Gp);
            gz = *(const float4*)(Gp + H_DIM);
            gn = *(const float4*)(Gp + 2 * H_DIM);
        } else {
            gr = bi_r; gz = bi_z; gn = bi_n;
        }
        float4 hold = *(const float4*)&Hin[(size_t)row * H_DIM + col];
        float o[4];
#pragma unroll
        for (int j = 0; j < TN; j++) {
            float ghr = acc[0][i][j] + ((const float*)&bh_r)[j];
            float ghz = acc[1][i][j] + ((const float*)&bh_z)[j];
            float ghn = acc[2][i][j] + ((const float*)&bh_n)[j];
            float r  = sigm(((const float*)&gr)[j] + ghr);
            float z  = sigm(((const float*)&gz)[j] + ghz);
            float nn = tanhf(((const float*)&gn)[j] + r * ghn);
            o[j] = (1.0f - z) * nn + z * ((const float*)&hold)[j];
        }
        *(float4*)&Hout[(size_t)row * H_DIM + col] = make_float4(o[0], o[1], o[2], o[3]);
    }
}

// ---------------------------------------------------------------------------
// Launch: proj -> step0 -> 15 x fused step (ping-pong, last writes d_out)
// ---------------------------------------------------------------------------
extern "C" void kernel_launch(void* const* d_in, const int* in_sizes, int n_in,
                              void* d_out, int out_size)
{
    const float* x   = (const float*)d_in[0];
    const float* Wih = (const float*)d_in[1];
    const float* Whh = (const float*)d_in[2];
    const float* bih = (const float*)d_in[3];
    const float* bhh = (const float*)d_in[4];
    float* out = (float*)d_out;

    dim3 grid(R_TOTAL / BM, H_DIM / BN);   // (128, 4)
    proj_kernel<<<grid, 256>>>(x, Wih, bih);
    step0_kernel<<<R_TOTAL, 256>>>(bih, bhh);
    for (int t = 1; t < KWIN; t++) {
        int in_idx = (t - 1) & 1;
        float* fin = (t == KWIN - 1) ? out : nullptr;
        step_kernel<<<grid, 256>>>(Whh, bih, bhh, t, in_idx, fin);
    }
}

// round 4
// speedup vs baseline: 2.9833x; 2.9833x over previous
#include <cuda_runtime.h>
#include <cstdint>

// Problem dims (fixed)
#define L_DIM   1024
#define H_DIM   256
#define KWIN    16
#define R_TOTAL 16384
#define G3      768
#define KDIM    256

// Tiling
#define TILE_M  128
#define NTOT    192                 // 3 gates x 64 cols
#define BK      32
#define NCHUNK  (KDIM / BK)         // 8
#define THREADS 512

// Smem (floats), padded stride 36 -> conflict-free fragment loads
#define AS      36
#define BS      36
#define ABUF    (TILE_M * AS)       // 4608
#define BBUF    (NTOT * BS)         // 6912
#define BUFF    (ABUF + BBUF)       // 11520
#define SMEM_BYTES (2 * BUFF * 4)   // 92160

// Scratch (allocation-free rule: device globals)
__device__ float g_G[R_TOTAL * G3];          // input projections incl. b_ih
__device__ float g_H[2][R_TOTAL * H_DIM];    // ping-pong hidden state

// ---------------------------------------------------------------------------
// helpers
// ---------------------------------------------------------------------------
__device__ __forceinline__ uint32_t smem_u32(const void* p) {
    uint32_t a;
    asm("{ .reg .u64 t; cvta.to.shared.u64 t, %1; cvt.u32.u64 %0, t; }" : "=r"(a) : "l"(p));
    return a;
}
__device__ __forceinline__ float tanh_apx(float x) {
    float y; asm("tanh.approx.f32 %0, %1;" : "=f"(y) : "f"(x)); return y;
}
__device__ __forceinline__ float sigm(float x) {
    return fmaf(tanh_apx(0.5f * x), 0.5f, 0.5f);
}

#define CP_ASYNC16(dst, src) \
    asm volatile("cp.async.cg.shared.global [%0], [%1], 16;" :: "r"(dst), "l"(src) : "memory")
#define CP_COMMIT() asm volatile("cp.async.commit_group;" ::: "memory")
#define CP_WAIT(n)  asm volatile("cp.async.wait_group %0;" :: "n"(n) : "memory")

__device__ __forceinline__ void mma_tf32(float* d, const uint32_t* a, uint32_t b0, uint32_t b1) {
    asm volatile(
        "mma.sync.aligned.m16n8k8.row.col.f32.tf32.tf32.f32 "
        "{%0,%1,%2,%3}, {%4,%5,%6,%7}, {%8,%9}, {%0,%1,%2,%3};"
        : "+f"(d[0]), "+f"(d[1]), "+f"(d[2]), "+f"(d[3])
        : "r"(a[0]), "r"(a[1]), "r"(a[2]), "r"(a[3]), "r"(b0), "r"(b1));
}

// ---------------------------------------------------------------------------
// Unified tf32 mma.sync GEMM [16384,256] x [768,256]^T with fused epilogue.
// mode==0: proj (A=X, W=W_ih, out = acc + b_ih -> g_G)
// mode==t: step (A=g_H[in_idx], W=W_hh, GRU update -> g_H[in_idx^1] or fin)
// ---------------------------------------------------------------------------
__global__ __launch_bounds__(THREADS, 1) void gemm3_kernel(
    const float* __restrict__ Aext,
    const float* __restrict__ W,
    const float* __restrict__ bih,
    const float* __restrict__ bhh,
    int mode, int in_idx, float* __restrict__ fin)
{
    extern __shared__ float smf[];
    const uint32_t sb = smem_u32(smf);
    const int tid = threadIdx.x;
    const int lane = tid & 31, wid = tid >> 5;
    const int warp_m = wid & 3;       // 4 x m32
    const int wn = wid >> 2;          // 4 x n16 (per gate)
    const int gm = blockIdx.x * TILE_M;
    const int n0 = blockIdx.y * 64;

    const float* __restrict__ A = (mode == 0) ? Aext : g_H[in_idx];

    // --- async tile loader: chunk [k0, k0+32) into buffer `buf` ---
    auto issue = [&](int k0, int buf) {
        const uint32_t abase = sb + buf * (BUFF * 4);
#pragma unroll
        for (int i = 0; i < 2; i++) {                 // A: 1024 x 16B
            int j = tid + i * THREADS;
            int row = j >> 3, kv = (j & 7) << 2;
            CP_ASYNC16(abase + (row * AS + kv) * 4,
                       &A[(size_t)(gm + row) * KDIM + k0 + kv]);
        }
        const uint32_t bbase = abase + ABUF * 4;
#pragma unroll
        for (int i = 0; i < 3; i++) {                 // B: 1536 x 16B
            int j = tid + i * THREADS;
            int row = j >> 3, kv = (j & 7) << 2;      // row = g*64 + nloc
            int g = row >> 6, nl = row & 63;
            CP_ASYNC16(bbase + (row * BS + kv) * 4,
                       &W[(size_t)(g * H_DIM + n0 + nl) * KDIM + k0 + kv]);
        }
        CP_COMMIT();
    };

    float acc[3][2][2][4];
#pragma unroll
    for (int g = 0; g < 3; g++)
#pragma unroll
        for (int mt = 0; mt < 2; mt++)
#pragma unroll
            for (int nt = 0; nt < 2; nt++)
#pragma unroll
                for (int e = 0; e < 4; e++) acc[g][mt][nt][e] = 0.0f;

    issue(0, 0);
    int buf = 0;
    for (int c = 0; c < NCHUNK; c++) {
        if (c < NCHUNK - 1) { issue((c + 1) * BK, buf ^ 1); CP_WAIT(1); }
        else                { CP_WAIT(0); }
        __syncthreads();

        const uint32_t* Ab = (const uint32_t*)(smf + buf * BUFF);
        const uint32_t* Bb = Ab + ABUF;
#pragma unroll
        for (int ks = 0; ks < 4; ks++) {
            const int kk = ks * 8 + (lane & 3);
            uint32_t a[2][4];
#pragma unroll
            for (int mt = 0; mt < 2; mt++) {
                int r0 = warp_m * 32 + mt * 16 + (lane >> 2);
                a[mt][0] = Ab[(r0)     * AS + kk];
                a[mt][1] = Ab[(r0 + 8) * AS + kk];
                a[mt][2] = Ab[(r0)     * AS + kk + 4];
                a[mt][3] = Ab[(r0 + 8) * AS + kk + 4];
            }
#pragma unroll
            for (int g = 0; g < 3; g++) {
#pragma unroll
                for (int nt = 0; nt < 2; nt++) {
                    int nr = g * 64 + wn * 16 + nt * 8 + (lane >> 2);
                    uint32_t b0 = Bb[nr * BS + kk];
                    uint32_t b1 = Bb[nr * BS + kk + 4];
                    mma_tf32(acc[g][0][nt], a[0], b0, b1);
                    mma_tf32(acc[g][1][nt], a[1], b0, b1);
                }
            }
        }
        __syncthreads();
        buf ^= 1;
    }

    // --- epilogue (warp-local; thread owns rows {rl, rl+8}, cols {cl, cl+1}) ---
    const int rl = lane >> 2, cl = (lane & 3) * 2;
    const int colb = wn * 16;

    if (mode == 0) {
#pragma unroll
        for (int mt = 0; mt < 2; mt++)
#pragma unroll
            for (int rp = 0; rp < 2; rp++) {
                int row = warp_m * 32 + mt * 16 + rp * 8 + rl;
                float* Gp = &g_G[(size_t)(gm + row) * G3];
#pragma unroll
                for (int g = 0; g < 3; g++)
#pragma unroll
                    for (int nt = 0; nt < 2; nt++) {
                        int col = n0 + colb + nt * 8 + cl;
                        float2 bv = *(const float2*)&bih[g * H_DIM + col];
                        float2 o;
                        o.x = acc[g][mt][nt][rp * 2 + 0] + bv.x;
                        o.y = acc[g][mt][nt][rp * 2 + 1] + bv.y;
                        *(float2*)&Gp[g * H_DIM + col] = o;
                    }
            }
    } else {
        const float* __restrict__ Hi = g_H[in_idx];
        float* __restrict__ Ho = fin ? fin : g_H[in_idx ^ 1];
#pragma unroll
        for (int mt = 0; mt < 2; mt++)
#pragma unroll
            for (int rp = 0; rp < 2; rp++) {
                int grow = gm + warp_m * 32 + mt * 16 + rp * 8 + rl;
                int l = grow & (L_DIM - 1);
                int src = l + mode - (KWIN - 1);
                const float* Gp = (src >= 0) ? &g_G[(size_t)(grow - l + src) * G3] : bih;
                const float* Hir = &Hi[(size_t)grow * H_DIM];
                float* Hor = &Ho[(size_t)grow * H_DIM];
#pragma unroll
                for (int nt = 0; nt < 2; nt++) {
                    int col = n0 + colb + nt * 8 + cl;
                    float2 gr = *(const float2*)&Gp[col];
                    float2 gz = *(const float2*)&Gp[H_DIM + col];
                    float2 gn = *(const float2*)&Gp[2 * H_DIM + col];
                    float2 br = *(const float2*)&bhh[col];
                    float2 bz = *(const float2*)&bhh[H_DIM + col];
                    float2 bn = *(const float2*)&bhh[2 * H_DIM + col];
                    float2 h  = *(const float2*)&Hir[col];
                    float2 o;
                    {
                        float r  = sigm(gr.x + acc[0][mt][nt][rp * 2] + br.x);
                        float z  = sigm(gz.x + acc[1][mt][nt][rp * 2] + bz.x);
                        float nn = tanh_apx(gn.x + r * (acc[2][mt][nt][rp * 2] + bn.x));
                        o.x = (1.0f - z) * nn + z * h.x;
                    }
                    {
                        float r  = sigm(gr.y + acc[0][mt][nt][rp * 2 + 1] + br.y);
                        float z  = sigm(gz.y + acc[1][mt][nt][rp * 2 + 1] + bz.y);
                        float nn = tanh_apx(gn.y + r * (acc[2][mt][nt][rp * 2 + 1] + bn.y));
                        o.y = (1.0f - z) * nn + z * h.y;
                    }
                    *(float2*)&Hor[col] = o;
                }
            }
    }
}

// ---------------------------------------------------------------------------
// Window step t=0 (h=0, pure elementwise)
// ---------------------------------------------------------------------------
__global__ __launch_bounds__(256) void step0_kernel(
    const float* __restrict__ bih, const float* __restrict__ bhh)
{
    const int row = blockIdx.x;
    const int col = threadIdx.x;
    const int l = row & (L_DIM - 1);
    const int src = l - (KWIN - 1);

    float gir, giz, gin;
    if (src >= 0) {
        const float* Gp = &g_G[(size_t)(row - l + src) * G3 + col];
        gir = Gp[0]; giz = Gp[H_DIM]; gin = Gp[2 * H_DIM];
    } else {
        gir = bih[col]; giz = bih[col + H_DIM]; gin = bih[col + 2 * H_DIM];
    }
    float r  = sigm(gir + bhh[col]);
    float z  = sigm(giz + bhh[col + H_DIM]);
    float nn = tanh_apx(gin + r * bhh[col + 2 * H_DIM]);
    g_H[0][(size_t)row * H_DIM + col] = (1.0f - z) * nn;
}

// ---------------------------------------------------------------------------
// Launch: proj -> step0 -> 15 x fused mma step (last writes d_out)
// ---------------------------------------------------------------------------
extern "C" void kernel_launch(void* const* d_in, const int* in_sizes, int n_in,
                              void* d_out, int out_size)
{
    const float* x   = (const float*)d_in[0];
    const float* Wih = (const float*)d_in[1];
    const float* Whh = (const float*)d_in[2];
    const float* bih = (const float*)d_in[3];
    const float* bhh = (const float*)d_in[4];
    float* out = (float*)d_out;

    cudaFuncSetAttribute(gemm3_kernel, cudaFuncAttributeMaxDynamicSharedMemorySize, SMEM_BYTES);

    dim3 grid(R_TOTAL / TILE_M, H_DIM / 64);   // (128, 4)
    gemm3_kernel<<<grid, THREADS, SMEM_BYTES>>>(x, Wih, bih, bhh, 0, 0, nullptr);
    step0_kernel<<<R_TOTAL, 256>>>(bih, bhh);
    for (int t = 1; t < KWIN; t++) {
        int in_idx = (t - 1) & 1;
        float* fin = (t == KWIN - 1) ? out : nullptr;
        gemm3_kernel<<<grid, THREADS, SMEM_BYTES>>>(nullptr, Whh, bih, bhh, t, in_idx, fin);
    }
}